// round 1
// baseline (speedup 1.0000x reference)
#include <cuda_runtime.h>
#include <cuda_bf16.h>

// ---------------------------------------------------------------------------
// 2-layer GCN:  out = Ahat( relu( Ahat(z W1) + b1 ) W2 ) + b2
// Ahat = D^-1/2 (A + I) D^-1/2, degree computed from dst column only.
//
// Restructure: y = dinv[row] * (x W).  Then per dst:
//   out[d] = dinv[d] * ( y[d]  +  sum_{edges s->d} y[s] ) + b
// Self-loop handled by initializing the scatter accumulator to y (second
// store in the GEMM epilogue). No per-edge multiply needed.
// ---------------------------------------------------------------------------

#define MAX_NODES 50048
#define D_IN   256
#define D_HID  256
#define D_OUT  128

// Scratch (static device globals — no runtime allocation allowed)
__device__ float g_deg [MAX_NODES];
__device__ float g_dinv[MAX_NODES];
__device__ float g_y1  [(size_t)MAX_NODES * D_HID];   // dinv-scaled z@W1
__device__ float g_acc1[(size_t)MAX_NODES * D_HID];   // scatter acc -> becomes h
__device__ float g_y2  [(size_t)MAX_NODES * D_OUT];   // dinv-scaled h@W2

// ---------------------------------------------------------------------------
// Degree / dinv
// ---------------------------------------------------------------------------
__global__ void init_deg_kernel(int n) {
    int i = blockIdx.x * blockDim.x + threadIdx.x;
    if (i < n) g_deg[i] = 1.0f;  // self-loop
}

__global__ void count_deg_kernel(const int* __restrict__ ei, int n_edges) {
    int e = blockIdx.x * blockDim.x + threadIdx.x;
    if (e < n_edges) atomicAdd(&g_deg[ei[n_edges + e]], 1.0f);
}

__global__ void dinv_kernel(int n) {
    int i = blockIdx.x * blockDim.x + threadIdx.x;
    if (i < n) g_dinv[i] = rsqrtf(g_deg[i]);
}

// ---------------------------------------------------------------------------
// SGEMM: Y[m,n] = ACC[m,n] = dinv[m] * sum_k A[m,k] * B[k,n]
// 128x128 block tile, BK=8, 256 threads, 8x8 per thread.
// ---------------------------------------------------------------------------
__device__ __forceinline__ void sgemm_body(const float* __restrict__ A,
                                           const float* __restrict__ B,
                                           const float* __restrict__ dinv,
                                           float* __restrict__ Y,
                                           float* __restrict__ ACC,
                                           int M, int N, int K)
{
    __shared__ float As[8][128];
    __shared__ float Bs[8][128];

    const int tid = threadIdx.x;
    const int tx  = tid & 15;       // 0..15 -> col group
    const int ty  = tid >> 4;       // 0..15 -> row group
    const int bm  = blockIdx.x * 128;
    const int bn  = blockIdx.y * 128;

    const int aRow = tid >> 1;            // 0..127
    const int aCol = (tid & 1) << 2;      // 0 or 4
    const int bRow = tid >> 5;            // 0..7
    const int bCol = (tid & 31) << 2;     // 0..124

    float acc[8][8];
#pragma unroll
    for (int i = 0; i < 8; i++)
#pragma unroll
        for (int j = 0; j < 8; j++) acc[i][j] = 0.0f;

    const int  arow_g = bm + aRow;
    const bool a_ok   = arow_g < M;
    const float* Aptr = A + (size_t)arow_g * K + aCol;

    for (int k0 = 0; k0 < K; k0 += 8) {
        float4 a4 = make_float4(0.f, 0.f, 0.f, 0.f);
        if (a_ok) a4 = *reinterpret_cast<const float4*>(Aptr + k0);
        float4 b4 = *reinterpret_cast<const float4*>(
            B + (size_t)(k0 + bRow) * N + bn + bCol);

        As[aCol + 0][aRow] = a4.x;
        As[aCol + 1][aRow] = a4.y;
        As[aCol + 2][aRow] = a4.z;
        As[aCol + 3][aRow] = a4.w;
        *reinterpret_cast<float4*>(&Bs[bRow][bCol]) = b4;
        __syncthreads();

#pragma unroll
        for (int kk = 0; kk < 8; kk++) {
            float af[8], bf[8];
#pragma unroll
            for (int i = 0; i < 8; i++) af[i] = As[kk][ty * 8 + i];
#pragma unroll
            for (int j = 0; j < 8; j++) bf[j] = Bs[kk][tx * 8 + j];
#pragma unroll
            for (int i = 0; i < 8; i++)
#pragma unroll
                for (int j = 0; j < 8; j++)
                    acc[i][j] = fmaf(af[i], bf[j], acc[i][j]);
        }
        __syncthreads();
    }

#pragma unroll
    for (int i = 0; i < 8; i++) {
        int r = bm + ty * 8 + i;
        if (r < M) {
            float s = dinv[r];
#pragma unroll
            for (int j = 0; j < 8; j += 4) {
                int c = bn + tx * 8 + j;
                float4 v;
                v.x = s * acc[i][j + 0];
                v.y = s * acc[i][j + 1];
                v.z = s * acc[i][j + 2];
                v.w = s * acc[i][j + 3];
                *reinterpret_cast<float4*>(Y   + (size_t)r * N + c) = v;
                *reinterpret_cast<float4*>(ACC + (size_t)r * N + c) = v;
            }
        }
    }
}

__global__ __launch_bounds__(256) void gemm1_kernel(const float* __restrict__ z,
                                                    const float* __restrict__ W1,
                                                    int M)
{
    sgemm_body(z, W1, g_dinv, g_y1, g_acc1, M, D_HID, D_IN);
}

__global__ __launch_bounds__(256) void gemm2_kernel(const float* __restrict__ W2,
                                                    float* __restrict__ out,
                                                    int M)
{
    sgemm_body(g_acc1, W2, g_dinv, g_y2, out, M, D_OUT, D_HID);
}

// ---------------------------------------------------------------------------
// Edge scatter: ACC[dst] += Y[src]  (vector float4 reductions, no return)
// One thread per (edge, float4-chunk). chunks = d/4 (power of two).
// ---------------------------------------------------------------------------
__device__ __forceinline__ void scatter_body(const int* __restrict__ ei,
                                             int n_edges,
                                             const float* __restrict__ Y,
                                             float* __restrict__ ACC,
                                             int log2chunks)
{
    const long long tid   = (long long)blockIdx.x * blockDim.x + threadIdx.x;
    const long long total = (long long)n_edges << log2chunks;
    if (tid >= total) return;
    const int chunks = 1 << log2chunks;
    const int e = (int)(tid >> log2chunks);
    const int c = (int)(tid & (chunks - 1));
    const int src = ei[e];
    const int dst = ei[n_edges + e];
    const float4 v = reinterpret_cast<const float4*>(Y)[(size_t)src * chunks + c];
    float4* p = reinterpret_cast<float4*>(ACC) + (size_t)dst * chunks + c;
    asm volatile("red.global.add.v4.f32 [%0], {%1, %2, %3, %4};"
                 :: "l"(p), "f"(v.x), "f"(v.y), "f"(v.z), "f"(v.w)
                 : "memory");
}

__global__ __launch_bounds__(256) void scatter1_kernel(const int* __restrict__ ei,
                                                       int n_edges)
{
    scatter_body(ei, n_edges, g_y1, g_acc1, 6);   // d=256 -> 64 chunks
}

__global__ __launch_bounds__(256) void scatter2_kernel(const int* __restrict__ ei,
                                                       int n_edges,
                                                       float* __restrict__ out)
{
    scatter_body(ei, n_edges, g_y2, out, 5);      // d=128 -> 32 chunks
}

// ---------------------------------------------------------------------------
// Finish passes
// ---------------------------------------------------------------------------
__global__ void finish1_kernel(const float* __restrict__ b1, int n_nodes) {
    long long idx = (long long)blockIdx.x * blockDim.x + threadIdx.x;
    if (idx >= (long long)n_nodes * D_HID) return;
    int i = (int)(idx >> 8);          // / 256
    int j = (int)(idx & 255);
    float v = g_dinv[i] * g_acc1[idx] + b1[j];
    g_acc1[idx] = fmaxf(v, 0.0f);     // acc1 becomes h (relu)
}

__global__ void finish2_kernel(float* __restrict__ out,
                               const float* __restrict__ b2, int n_nodes) {
    long long idx = (long long)blockIdx.x * blockDim.x + threadIdx.x;
    if (idx >= (long long)n_nodes * D_OUT) return;
    int i = (int)(idx >> 7);          // / 128
    int j = (int)(idx & 127);
    out[idx] = g_dinv[i] * out[idx] + b2[j];
}

// ---------------------------------------------------------------------------
// Launch
// ---------------------------------------------------------------------------
extern "C" void kernel_launch(void* const* d_in, const int* in_sizes, int n_in,
                              void* d_out, int out_size)
{
    const float* z   = (const float*)d_in[0];
    const int*   ei  = (const int*)  d_in[1];
    const float* W1  = (const float*)d_in[2];
    const float* b1  = (const float*)d_in[3];
    const float* W2  = (const float*)d_in[4];
    const float* b2  = (const float*)d_in[5];
    float* out = (float*)d_out;

    const int n_nodes = in_sizes[0] / D_IN;
    const int n_edges = in_sizes[1] / 2;

    const int T = 256;

    // degree + dinv
    init_deg_kernel<<<(n_nodes + T - 1) / T, T>>>(n_nodes);
    count_deg_kernel<<<(n_edges + T - 1) / T, T>>>(ei, n_edges);
    dinv_kernel<<<(n_nodes + T - 1) / T, T>>>(n_nodes);

    // layer 1
    {
        dim3 grid((n_nodes + 127) / 128, D_HID / 128);
        gemm1_kernel<<<grid, 256>>>(z, W1, n_nodes);
    }
    {
        long long total = (long long)n_edges << 6;
        scatter1_kernel<<<(unsigned)((total + T - 1) / T), T>>>(ei, n_edges);
    }
    {
        long long total = (long long)n_nodes * D_HID;
        finish1_kernel<<<(unsigned)((total + T - 1) / T), T>>>(b1, n_nodes);
    }

    // layer 2
    {
        dim3 grid((n_nodes + 127) / 128, D_OUT / 128);
        gemm2_kernel<<<grid, 256>>>(W2, out, n_nodes);
    }
    {
        long long total = (long long)n_edges << 5;
        scatter2_kernel<<<(unsigned)((total + T - 1) / T), T>>>(ei, n_edges, out);
    }
    {
        long long total = (long long)n_nodes * D_OUT;
        finish2_kernel<<<(unsigned)((total + T - 1) / T), T>>>(out, b2, n_nodes);
    }
}

// round 2
// speedup vs baseline: 1.3291x; 1.3291x over previous
#include <cuda_runtime.h>
#include <cuda_bf16.h>

// ---------------------------------------------------------------------------
// 2-layer GCN:  out = Ahat( relu( Ahat(z W1) + b1 ) W2 ) + b2
// Ahat = D^-1/2 (A + I) D^-1/2.
//
// Restructure: y = dinv[row] * (x W).  Then per dst:
//   out[d] = dinv[d] * ( y[d]  +  sum_{edges s->d} y[s] ) + b
// Self-loop handled by initializing scatter accumulator to y (second store
// in GEMM epilogue).  GEMMs now on tensor cores (mma.sync tf32).
// ---------------------------------------------------------------------------

#define MAX_NODES 50048
#define D_IN   256
#define D_HID  256
#define D_OUT  128

__device__ float g_deg [MAX_NODES];
__device__ float g_dinv[MAX_NODES];
__device__ float g_y1  [(size_t)MAX_NODES * D_HID];
__device__ float g_acc1[(size_t)MAX_NODES * D_HID];
__device__ float g_y2  [(size_t)MAX_NODES * D_OUT];

// ---------------------------------------------------------------------------
__global__ void init_deg_kernel(int n) {
    int i = blockIdx.x * blockDim.x + threadIdx.x;
    if (i < n) g_deg[i] = 1.0f;
}
__global__ void count_deg_kernel(const int* __restrict__ ei, int n_edges) {
    int e = blockIdx.x * blockDim.x + threadIdx.x;
    if (e < n_edges) atomicAdd(&g_deg[ei[n_edges + e]], 1.0f);
}
__global__ void dinv_kernel(int n) {
    int i = blockIdx.x * blockDim.x + threadIdx.x;
    if (i < n) g_dinv[i] = rsqrtf(g_deg[i]);
}

// ---------------------------------------------------------------------------
// TF32 tensor-core GEMM: Y = ACC = dinv[m] * (A @ B)
// BM=128, BN=128, BK=16, 256 threads, warp grid 4x2, warp tile 32x64.
// mma.sync.aligned.m16n8k8.row.col.f32.tf32.tf32.f32
// ---------------------------------------------------------------------------
__device__ __forceinline__ unsigned f2tf32(float x) {
    unsigned u;
    asm("cvt.rna.tf32.f32 %0, %1;" : "=r"(u) : "f"(x));
    return u;
}

__device__ __forceinline__ void mma_tf32(float c[4],
                                         unsigned a0, unsigned a1,
                                         unsigned a2, unsigned a3,
                                         unsigned b0, unsigned b1) {
    asm volatile(
        "mma.sync.aligned.m16n8k8.row.col.f32.tf32.tf32.f32 "
        "{%0,%1,%2,%3}, {%4,%5,%6,%7}, {%8,%9}, {%0,%1,%2,%3};"
        : "+f"(c[0]), "+f"(c[1]), "+f"(c[2]), "+f"(c[3])
        : "r"(a0), "r"(a1), "r"(a2), "r"(a3), "r"(b0), "r"(b1));
}

__device__ __forceinline__ void mma_gemm_body(const float* __restrict__ A,
                                              const float* __restrict__ B,
                                              const float* __restrict__ dinv,
                                              float* __restrict__ Y,
                                              float* __restrict__ ACC,
                                              int M, int N, int K)
{
    // smem tiles stored as [k][m]/[k][n], padded to 132 floats
    __shared__ unsigned As[2][16][132];
    __shared__ unsigned Bs[2][16][132];

    const int tid  = threadIdx.x;
    const int lane = tid & 31;
    const int warp = tid >> 5;
    const int g    = lane >> 2;      // group id (row within 8)
    const int tig  = lane & 3;       // thread in group (k)
    const int wm   = (warp & 3) * 32;
    const int wn   = (warp >> 2) * 64;
    const int bm   = blockIdx.x * 128;
    const int bn   = blockIdx.y * 128;

    float acc[2][8][4];
#pragma unroll
    for (int mt = 0; mt < 2; mt++)
#pragma unroll
        for (int nt = 0; nt < 8; nt++)
#pragma unroll
            for (int q = 0; q < 4; q++) acc[mt][nt][q] = 0.0f;

    const int nk = K / 16;

    // staging registers for prefetch
    float4 pa[2], pb[2];

    // ---- load tile 0 ----
    {
#pragma unroll
        for (int u = 0; u < 2; u++) {
            int i = 2 * tid + u;                 // A f4 id
            int r = i >> 2, kc = (i & 3) << 2;
            int gr = bm + r;
            float4 v = make_float4(0.f, 0.f, 0.f, 0.f);
            if (gr < M) v = *reinterpret_cast<const float4*>(A + (size_t)gr * K + kc);
            pa[u] = v;
            int k = i >> 5, n4 = i & 31;         // B f4 id
            pb[u] = *reinterpret_cast<const float4*>(B + (size_t)k * N + bn + n4 * 4);
        }
#pragma unroll
        for (int u = 0; u < 2; u++) {
            int i = 2 * tid + u;
            int r = i >> 2, kc = (i & 3) << 2;
            As[0][kc + 0][r] = f2tf32(pa[u].x);
            As[0][kc + 1][r] = f2tf32(pa[u].y);
            As[0][kc + 2][r] = f2tf32(pa[u].z);
            As[0][kc + 3][r] = f2tf32(pa[u].w);
            int k = i >> 5, n4 = i & 31;
            unsigned* p = &Bs[0][k][n4 * 4];
            p[0] = f2tf32(pb[u].x);
            p[1] = f2tf32(pb[u].y);
            p[2] = f2tf32(pb[u].z);
            p[3] = f2tf32(pb[u].w);
        }
    }
    __syncthreads();

    int cur = 0;
    for (int t = 0; t < nk; t++) {
        // prefetch next tile into registers
        if (t + 1 < nk) {
            int k0 = (t + 1) * 16;
#pragma unroll
            for (int u = 0; u < 2; u++) {
                int i = 2 * tid + u;
                int r = i >> 2, kc = (i & 3) << 2;
                int gr = bm + r;
                float4 v = make_float4(0.f, 0.f, 0.f, 0.f);
                if (gr < M) v = *reinterpret_cast<const float4*>(A + (size_t)gr * K + k0 + kc);
                pa[u] = v;
                int k = i >> 5, n4 = i & 31;
                pb[u] = *reinterpret_cast<const float4*>(B + (size_t)(k0 + k) * N + bn + n4 * 4);
            }
        }

        // compute: 2 k-steps of 8
#pragma unroll
        for (int ks = 0; ks < 2; ks++) {
            const int k = ks * 8;
            unsigned af[2][4];
#pragma unroll
            for (int mt = 0; mt < 2; mt++) {
                int mb = wm + mt * 16 + g;
                af[mt][0] = As[cur][k + tig][mb];
                af[mt][1] = As[cur][k + tig][mb + 8];
                af[mt][2] = As[cur][k + tig + 4][mb];
                af[mt][3] = As[cur][k + tig + 4][mb + 8];
            }
            unsigned bf[8][2];
#pragma unroll
            for (int nt = 0; nt < 8; nt++) {
                int nb = wn + nt * 8 + g;
                bf[nt][0] = Bs[cur][k + tig][nb];
                bf[nt][1] = Bs[cur][k + tig + 4][nb];
            }
#pragma unroll
            for (int mt = 0; mt < 2; mt++)
#pragma unroll
                for (int nt = 0; nt < 8; nt++)
                    mma_tf32(acc[mt][nt],
                             af[mt][0], af[mt][1], af[mt][2], af[mt][3],
                             bf[nt][0], bf[nt][1]);
        }

        if (t + 1 < nk) {
            int nxt = cur ^ 1;
#pragma unroll
            for (int u = 0; u < 2; u++) {
                int i = 2 * tid + u;
                int r = i >> 2, kc = (i & 3) << 2;
                As[nxt][kc + 0][r] = f2tf32(pa[u].x);
                As[nxt][kc + 1][r] = f2tf32(pa[u].y);
                As[nxt][kc + 2][r] = f2tf32(pa[u].z);
                As[nxt][kc + 3][r] = f2tf32(pa[u].w);
                int k = i >> 5, n4 = i & 31;
                unsigned* p = &Bs[nxt][k][n4 * 4];
                p[0] = f2tf32(pb[u].x);
                p[1] = f2tf32(pb[u].y);
                p[2] = f2tf32(pb[u].z);
                p[3] = f2tf32(pb[u].w);
            }
            __syncthreads();
            cur = nxt;
        }
    }

    // ---- epilogue: scale by dinv, store to Y and ACC ----
#pragma unroll
    for (int mt = 0; mt < 2; mt++) {
        int r0 = bm + wm + mt * 16 + g;
        int r1 = r0 + 8;
        float s0 = (r0 < M) ? dinv[r0] : 0.0f;
        float s1 = (r1 < M) ? dinv[r1] : 0.0f;
#pragma unroll
        for (int nt = 0; nt < 8; nt++) {
            int c = bn + wn + nt * 8 + 2 * tig;
            if (r0 < M) {
                float2 v0 = make_float2(s0 * acc[mt][nt][0], s0 * acc[mt][nt][1]);
                *reinterpret_cast<float2*>(Y   + (size_t)r0 * N + c) = v0;
                *reinterpret_cast<float2*>(ACC + (size_t)r0 * N + c) = v0;
            }
            if (r1 < M) {
                float2 v1 = make_float2(s1 * acc[mt][nt][2], s1 * acc[mt][nt][3]);
                *reinterpret_cast<float2*>(Y   + (size_t)r1 * N + c) = v1;
                *reinterpret_cast<float2*>(ACC + (size_t)r1 * N + c) = v1;
            }
        }
    }
}

__global__ __launch_bounds__(256) void gemm1_kernel(const float* __restrict__ z,
                                                    const float* __restrict__ W1,
                                                    int M)
{
    mma_gemm_body(z, W1, g_dinv, g_y1, g_acc1, M, D_HID, D_IN);
}

__global__ __launch_bounds__(256) void gemm2_kernel(const float* __restrict__ W2,
                                                    float* __restrict__ out,
                                                    int M)
{
    mma_gemm_body(g_acc1, W2, g_dinv, g_y2, out, M, D_OUT, D_HID);
}

// ---------------------------------------------------------------------------
// Edge scatter: ACC[dst] += Y[src]  (float4 reductions, no return value)
// ---------------------------------------------------------------------------
__device__ __forceinline__ void scatter_body(const int* __restrict__ ei,
                                             int n_edges,
                                             const float* __restrict__ Y,
                                             float* __restrict__ ACC,
                                             int log2chunks)
{
    const long long tid   = (long long)blockIdx.x * blockDim.x + threadIdx.x;
    const long long total = (long long)n_edges << log2chunks;
    if (tid >= total) return;
    const int chunks = 1 << log2chunks;
    const int e = (int)(tid >> log2chunks);
    const int c = (int)(tid & (chunks - 1));
    const int src = ei[e];
    const int dst = ei[n_edges + e];
    const float4 v = reinterpret_cast<const float4*>(Y)[(size_t)src * chunks + c];
    float4* p = reinterpret_cast<float4*>(ACC) + (size_t)dst * chunks + c;
    asm volatile("red.global.add.v4.f32 [%0], {%1, %2, %3, %4};"
                 :: "l"(p), "f"(v.x), "f"(v.y), "f"(v.z), "f"(v.w)
                 : "memory");
}

__global__ __launch_bounds__(256) void scatter1_kernel(const int* __restrict__ ei,
                                                       int n_edges)
{
    scatter_body(ei, n_edges, g_y1, g_acc1, 6);
}

__global__ __launch_bounds__(256) void scatter2_kernel(const int* __restrict__ ei,
                                                       int n_edges,
                                                       float* __restrict__ out)
{
    scatter_body(ei, n_edges, g_y2, out, 5);
}

// ---------------------------------------------------------------------------
__global__ void finish1_kernel(const float* __restrict__ b1, int n_nodes) {
    long long idx = (long long)blockIdx.x * blockDim.x + threadIdx.x;
    if (idx >= (long long)n_nodes * D_HID) return;
    int i = (int)(idx >> 8);
    int j = (int)(idx & 255);
    float v = g_dinv[i] * g_acc1[idx] + b1[j];
    g_acc1[idx] = fmaxf(v, 0.0f);
}

__global__ void finish2_kernel(float* __restrict__ out,
                               const float* __restrict__ b2, int n_nodes) {
    long long idx = (long long)blockIdx.x * blockDim.x + threadIdx.x;
    if (idx >= (long long)n_nodes * D_OUT) return;
    int i = (int)(idx >> 7);
    int j = (int)(idx & 127);
    out[idx] = g_dinv[i] * out[idx] + b2[j];
}

// ---------------------------------------------------------------------------
extern "C" void kernel_launch(void* const* d_in, const int* in_sizes, int n_in,
                              void* d_out, int out_size)
{
    const float* z   = (const float*)d_in[0];
    const int*   ei  = (const int*)  d_in[1];
    const float* W1  = (const float*)d_in[2];
    const float* b1  = (const float*)d_in[3];
    const float* W2  = (const float*)d_in[4];
    const float* b2  = (const float*)d_in[5];
    float* out = (float*)d_out;

    const int n_nodes = in_sizes[0] / D_IN;
    const int n_edges = in_sizes[1] / 2;
    const int T = 256;

    init_deg_kernel<<<(n_nodes + T - 1) / T, T>>>(n_nodes);
    count_deg_kernel<<<(n_edges + T - 1) / T, T>>>(ei, n_edges);
    dinv_kernel<<<(n_nodes + T - 1) / T, T>>>(n_nodes);

    {
        dim3 grid((n_nodes + 127) / 128, D_HID / 128);
        gemm1_kernel<<<grid, 256>>>(z, W1, n_nodes);
    }
    {
        long long total = (long long)n_edges << 6;
        scatter1_kernel<<<(unsigned)((total + T - 1) / T), T>>>(ei, n_edges);
    }
    {
        long long total = (long long)n_nodes * D_HID;
        finish1_kernel<<<(unsigned)((total + T - 1) / T), T>>>(b1, n_nodes);
    }
    {
        dim3 grid((n_nodes + 127) / 128, D_OUT / 128);
        gemm2_kernel<<<grid, 256>>>(W2, out, n_nodes);
    }
    {
        long long total = (long long)n_edges << 5;
        scatter2_kernel<<<(unsigned)((total + T - 1) / T), T>>>(ei, n_edges, out);
    }
    {
        long long total = (long long)n_nodes * D_OUT;
        finish2_kernel<<<(unsigned)((total + T - 1) / T), T>>>(out, b2, n_nodes);
    }
}

// round 4
// speedup vs baseline: 2.5647x; 1.9297x over previous
#include <cuda_runtime.h>
#include <cuda_bf16.h>

// ---------------------------------------------------------------------------
// 2-layer GCN via CSR aggregation:
//   y = dinv[row] * (x W)            (tf32 tensor-core GEMM, fused scale)
//   out[d] = dinv[d]*(y[d] + sum_{s->d} y[s]) + b   (warp-per-row gather)
// CSR (dst-sorted) built on device each launch; no atomics in aggregation.
//
// RULE: __device__ globals are ONLY referenced from device code (kernel
// bodies). Never passed as kernel arguments from kernel_launch (host code) —
// that passes the host shadow address and silently reads garbage.
// ---------------------------------------------------------------------------

#define MAX_NODES 50048
#define MAX_EDGES 1048576
#define D_IN   256
#define D_HID  256
#define D_OUT  128
#define SCAN_B ((MAX_NODES + 255) / 256)

__device__ float g_dinv[MAX_NODES];
__device__ int   g_cnt [MAX_NODES];
__device__ int   g_tmp [MAX_NODES];
__device__ int   g_bsum[SCAN_B];
__device__ int   g_rowptr[MAX_NODES + 1];
__device__ int   g_wofs[MAX_NODES];
__device__ int   g_col [MAX_EDGES];
__device__ float g_y1  [(size_t)MAX_NODES * D_HID];
__device__ float g_h   [(size_t)MAX_NODES * D_HID];
__device__ float g_y2  [(size_t)MAX_NODES * D_OUT];

// ---------------------------------------------------------------------------
// CSR build
// ---------------------------------------------------------------------------
__global__ void zero_cnt_kernel(int n) {
    int i = blockIdx.x * blockDim.x + threadIdx.x;
    if (i < n) g_cnt[i] = 0;
}

__global__ void count_kernel(const int* __restrict__ ei, int n_edges) {
    int e = blockIdx.x * blockDim.x + threadIdx.x;
    if (e < n_edges) atomicAdd(&g_cnt[ei[n_edges + e]], 1);
}

__global__ void dinv_kernel(int n) {
    int i = blockIdx.x * blockDim.x + threadIdx.x;
    if (i < n) g_dinv[i] = rsqrtf((float)(g_cnt[i] + 1));   // +1 self-loop
}

__global__ void scan1_kernel(int n) {
    __shared__ int sh[256];
    int i = blockIdx.x * 256 + threadIdx.x;
    int v = (i < n) ? g_cnt[i] : 0;
    sh[threadIdx.x] = v;
    __syncthreads();
#pragma unroll
    for (int off = 1; off < 256; off <<= 1) {
        int t = (threadIdx.x >= off) ? sh[threadIdx.x - off] : 0;
        __syncthreads();
        sh[threadIdx.x] += t;
        __syncthreads();
    }
    if (i < n) g_tmp[i] = sh[threadIdx.x];
    if (threadIdx.x == 255) g_bsum[blockIdx.x] = sh[255];
}

__global__ void scan2_kernel(int nb) {
    __shared__ int sh[256];
    int t = threadIdx.x;
    int v = (t < nb) ? g_bsum[t] : 0;
    sh[t] = v;
    __syncthreads();
#pragma unroll
    for (int off = 1; off < 256; off <<= 1) {
        int u = (t >= off) ? sh[t - off] : 0;
        __syncthreads();
        sh[t] += u;
        __syncthreads();
    }
    int ex = (t == 0) ? 0 : sh[t - 1];
    if (t < nb) g_bsum[t] = ex;
}

__global__ void scan3_kernel(int n) {
    int i = blockIdx.x * 256 + threadIdx.x;
    if (i < n) {
        int incl = g_tmp[i] + g_bsum[blockIdx.x];
        g_rowptr[i + 1] = incl;
        g_wofs[i] = incl - g_cnt[i];
        if (i == 0) g_rowptr[0] = 0;
    }
}

__global__ void fill_kernel(const int* __restrict__ ei, int n_edges) {
    int e = blockIdx.x * blockDim.x + threadIdx.x;
    if (e < n_edges) {
        int dst = ei[n_edges + e];
        int pos = atomicAdd(&g_wofs[dst], 1);
        g_col[pos] = ei[e];
    }
}

// ---------------------------------------------------------------------------
// TF32 tensor-core GEMM: Y = dinv[m] * (A @ B)
// ---------------------------------------------------------------------------
__device__ __forceinline__ unsigned f2tf32(float x) {
    unsigned u;
    asm("cvt.rna.tf32.f32 %0, %1;" : "=r"(u) : "f"(x));
    return u;
}

__device__ __forceinline__ void mma_tf32(float c[4],
                                         unsigned a0, unsigned a1,
                                         unsigned a2, unsigned a3,
                                         unsigned b0, unsigned b1) {
    asm volatile(
        "mma.sync.aligned.m16n8k8.row.col.f32.tf32.tf32.f32 "
        "{%0,%1,%2,%3}, {%4,%5,%6,%7}, {%8,%9}, {%0,%1,%2,%3};"
        : "+f"(c[0]), "+f"(c[1]), "+f"(c[2]), "+f"(c[3])
        : "r"(a0), "r"(a1), "r"(a2), "r"(a3), "r"(b0), "r"(b1));
}

__device__ __forceinline__ void mma_gemm_body(const float* __restrict__ A,
                                              const float* __restrict__ B,
                                              const float* __restrict__ dinv,
                                              float* __restrict__ Y,
                                              int M, int N, int K)
{
    __shared__ unsigned As[2][16][132];
    __shared__ unsigned Bs[2][16][132];

    const int tid  = threadIdx.x;
    const int lane = tid & 31;
    const int warp = tid >> 5;
    const int g    = lane >> 2;
    const int tig  = lane & 3;
    const int wm   = (warp & 3) * 32;
    const int wn   = (warp >> 2) * 64;
    const int bm   = blockIdx.x * 128;
    const int bn   = blockIdx.y * 128;

    float acc[2][8][4];
#pragma unroll
    for (int mt = 0; mt < 2; mt++)
#pragma unroll
        for (int nt = 0; nt < 8; nt++)
#pragma unroll
            for (int q = 0; q < 4; q++) acc[mt][nt][q] = 0.0f;

    const int nk = K / 16;
    float4 pa[2], pb[2];

    {
#pragma unroll
        for (int u = 0; u < 2; u++) {
            int i = 2 * tid + u;
            int r = i >> 2, kc = (i & 3) << 2;
            int gr = bm + r;
            float4 v = make_float4(0.f, 0.f, 0.f, 0.f);
            if (gr < M) v = *reinterpret_cast<const float4*>(A + (size_t)gr * K + kc);
            pa[u] = v;
            int k = i >> 5, n4 = i & 31;
            pb[u] = *reinterpret_cast<const float4*>(B + (size_t)k * N + bn + n4 * 4);
        }
#pragma unroll
        for (int u = 0; u < 2; u++) {
            int i = 2 * tid + u;
            int r = i >> 2, kc = (i & 3) << 2;
            As[0][kc + 0][r] = f2tf32(pa[u].x);
            As[0][kc + 1][r] = f2tf32(pa[u].y);
            As[0][kc + 2][r] = f2tf32(pa[u].z);
            As[0][kc + 3][r] = f2tf32(pa[u].w);
            int k = i >> 5, n4 = i & 31;
            unsigned* p = &Bs[0][k][n4 * 4];
            p[0] = f2tf32(pb[u].x);
            p[1] = f2tf32(pb[u].y);
            p[2] = f2tf32(pb[u].z);
            p[3] = f2tf32(pb[u].w);
        }
    }
    __syncthreads();

    int cur = 0;
    for (int t = 0; t < nk; t++) {
        if (t + 1 < nk) {
            int k0 = (t + 1) * 16;
#pragma unroll
            for (int u = 0; u < 2; u++) {
                int i = 2 * tid + u;
                int r = i >> 2, kc = (i & 3) << 2;
                int gr = bm + r;
                float4 v = make_float4(0.f, 0.f, 0.f, 0.f);
                if (gr < M) v = *reinterpret_cast<const float4*>(A + (size_t)gr * K + k0 + kc);
                pa[u] = v;
                int k = i >> 5, n4 = i & 31;
                pb[u] = *reinterpret_cast<const float4*>(B + (size_t)(k0 + k) * N + bn + n4 * 4);
            }
        }

#pragma unroll
        for (int ks = 0; ks < 2; ks++) {
            const int k = ks * 8;
            unsigned af[2][4];
#pragma unroll
            for (int mt = 0; mt < 2; mt++) {
                int mb = wm + mt * 16 + g;
                af[mt][0] = As[cur][k + tig][mb];
                af[mt][1] = As[cur][k + tig][mb + 8];
                af[mt][2] = As[cur][k + tig + 4][mb];
                af[mt][3] = As[cur][k + tig + 4][mb + 8];
            }
            unsigned bf[8][2];
#pragma unroll
            for (int nt = 0; nt < 8; nt++) {
                int nb = wn + nt * 8 + g;
                bf[nt][0] = Bs[cur][k + tig][nb];
                bf[nt][1] = Bs[cur][k + tig + 4][nb];
            }
#pragma unroll
            for (int mt = 0; mt < 2; mt++)
#pragma unroll
                for (int nt = 0; nt < 8; nt++)
                    mma_tf32(acc[mt][nt],
                             af[mt][0], af[mt][1], af[mt][2], af[mt][3],
                             bf[nt][0], bf[nt][1]);
        }

        if (t + 1 < nk) {
            int nxt = cur ^ 1;
#pragma unroll
            for (int u = 0; u < 2; u++) {
                int i = 2 * tid + u;
                int r = i >> 2, kc = (i & 3) << 2;
                As[nxt][kc + 0][r] = f2tf32(pa[u].x);
                As[nxt][kc + 1][r] = f2tf32(pa[u].y);
                As[nxt][kc + 2][r] = f2tf32(pa[u].z);
                As[nxt][kc + 3][r] = f2tf32(pa[u].w);
                int k = i >> 5, n4 = i & 31;
                unsigned* p = &Bs[nxt][k][n4 * 4];
                p[0] = f2tf32(pb[u].x);
                p[1] = f2tf32(pb[u].y);
                p[2] = f2tf32(pb[u].z);
                p[3] = f2tf32(pb[u].w);
            }
            __syncthreads();
            cur = nxt;
        }
    }

#pragma unroll
    for (int mt = 0; mt < 2; mt++) {
        int r0 = bm + wm + mt * 16 + g;
        int r1 = r0 + 8;
        float s0 = (r0 < M) ? dinv[r0] : 0.0f;
        float s1 = (r1 < M) ? dinv[r1] : 0.0f;
#pragma unroll
        for (int nt = 0; nt < 8; nt++) {
            int c = bn + wn + nt * 8 + 2 * tig;
            if (r0 < M)
                *reinterpret_cast<float2*>(Y + (size_t)r0 * N + c) =
                    make_float2(s0 * acc[mt][nt][0], s0 * acc[mt][nt][1]);
            if (r1 < M)
                *reinterpret_cast<float2*>(Y + (size_t)r1 * N + c) =
                    make_float2(s1 * acc[mt][nt][2], s1 * acc[mt][nt][3]);
        }
    }
}

__global__ __launch_bounds__(256) void gemm1_kernel(const float* __restrict__ z,
                                                    const float* __restrict__ W1,
                                                    int M)
{
    mma_gemm_body(z, W1, g_dinv, g_y1, M, D_HID, D_IN);
}

__global__ __launch_bounds__(256) void gemm2_kernel(const float* __restrict__ W2,
                                                    int M)
{
    mma_gemm_body(g_h, W2, g_dinv, g_y2, M, D_OUT, D_HID);
}

// ---------------------------------------------------------------------------
// CSR aggregation: OUT[d] = dinv[d]*(Y[d] + sum_{s in csr[d]} Y[s]) + bias
// One warp per (node, 128-feature chunk); float4 per lane.
// Y/OUT are device-side arguments (bound inside __global__ wrappers below).
// ---------------------------------------------------------------------------
template<int D, bool RELU>
__device__ __forceinline__ void agg_body(const float* __restrict__ Y,
                                         float* __restrict__ OUT,
                                         const float* __restrict__ bias,
                                         int n_nodes)
{
    constexpr int CHUNKS = D / 128;
    const int w    = (blockIdx.x * blockDim.x + threadIdx.x) >> 5;
    const int lane = threadIdx.x & 31;
    const int node = w / CHUNKS;
    if (node >= n_nodes) return;
    const int f4 = (w % CHUNKS) * 32 + lane;
    constexpr int RS = D / 4;

    const float4* Yv = reinterpret_cast<const float4*>(Y);

    float4 a = Yv[(size_t)node * RS + f4];           // self-loop
    const int e0 = g_rowptr[node];
    const int e1 = g_rowptr[node + 1];

    int e = e0;
    if (e + 1 < e1) {
        int s0 = g_col[e], s1 = g_col[e + 1];
        float4 v0 = Yv[(size_t)s0 * RS + f4];
        float4 v1 = Yv[(size_t)s1 * RS + f4];
        e += 2;
        for (; e + 1 < e1; e += 2) {
            int n0 = g_col[e], n1 = g_col[e + 1];
            float4 w0 = Yv[(size_t)n0 * RS + f4];
            float4 w1 = Yv[(size_t)n1 * RS + f4];
            a.x += v0.x + v1.x; a.y += v0.y + v1.y;
            a.z += v0.z + v1.z; a.w += v0.w + v1.w;
            v0 = w0; v1 = w1;
        }
        a.x += v0.x + v1.x; a.y += v0.y + v1.y;
        a.z += v0.z + v1.z; a.w += v0.w + v1.w;
    }
    if (e < e1) {
        float4 v = Yv[(size_t)g_col[e] * RS + f4];
        a.x += v.x; a.y += v.y; a.z += v.z; a.w += v.w;
    }

    const float s = g_dinv[node];
    const float4 b4 = reinterpret_cast<const float4*>(bias)[f4];
    float4 o;
    o.x = fmaf(s, a.x, b4.x);
    o.y = fmaf(s, a.y, b4.y);
    o.z = fmaf(s, a.z, b4.z);
    o.w = fmaf(s, a.w, b4.w);
    if (RELU) {
        o.x = fmaxf(o.x, 0.f); o.y = fmaxf(o.y, 0.f);
        o.z = fmaxf(o.z, 0.f); o.w = fmaxf(o.w, 0.f);
    }
    reinterpret_cast<float4*>(OUT)[(size_t)node * RS + f4] = o;
}

__global__ __launch_bounds__(256) void agg1_kernel(const float* __restrict__ bias,
                                                   int n_nodes)
{
    agg_body<D_HID, true>(g_y1, g_h, bias, n_nodes);
}

__global__ __launch_bounds__(256) void agg2_kernel(float* __restrict__ out,
                                                   const float* __restrict__ bias,
                                                   int n_nodes)
{
    agg_body<D_OUT, false>(g_y2, out, bias, n_nodes);
}

// ---------------------------------------------------------------------------
extern "C" void kernel_launch(void* const* d_in, const int* in_sizes, int n_in,
                              void* d_out, int out_size)
{
    const float* z   = (const float*)d_in[0];
    const int*   ei  = (const int*)  d_in[1];
    const float* W1  = (const float*)d_in[2];
    const float* b1  = (const float*)d_in[3];
    const float* W2  = (const float*)d_in[4];
    const float* b2  = (const float*)d_in[5];
    float* out = (float*)d_out;

    const int n_nodes = in_sizes[0] / D_IN;
    const int n_edges = in_sizes[1] / 2;
    const int T  = 256;
    const int nbN = (n_nodes + T - 1) / T;
    const int nbE = (n_edges + T - 1) / T;

    // ---- CSR build + dinv ----
    zero_cnt_kernel<<<nbN, T>>>(n_nodes);
    count_kernel<<<nbE, T>>>(ei, n_edges);
    dinv_kernel<<<nbN, T>>>(n_nodes);
    scan1_kernel<<<nbN, T>>>(n_nodes);
    scan2_kernel<<<1, T>>>(nbN);
    scan3_kernel<<<nbN, T>>>(n_nodes);
    fill_kernel<<<nbE, T>>>(ei, n_edges);

    // ---- layer 1 ----
    {
        dim3 grid((n_nodes + 127) / 128, D_HID / 128);
        gemm1_kernel<<<grid, 256>>>(z, W1, n_nodes);
    }
    {
        long long thr = (long long)n_nodes * (D_HID / 128) * 32;
        agg1_kernel<<<(unsigned)((thr + T - 1) / T), T>>>(b1, n_nodes);
    }

    // ---- layer 2 ----
    {
        dim3 grid((n_nodes + 127) / 128, D_OUT / 128);
        gemm2_kernel<<<grid, 256>>>(W2, n_nodes);
    }
    {
        long long thr = (long long)n_nodes * (D_OUT / 128) * 32;
        agg2_kernel<<<(unsigned)((thr + T - 1) / T), T>>>(out, b2, n_nodes);
    }
}